// round 1
// baseline (speedup 1.0000x reference)
#include <cuda_runtime.h>

#define Bb 2
#define Ss 2048
#define Dd 1024
#define Hh 16
#define DHh 64
#define NBb 32
#define MLPD 4096
#define BS (Bb*Ss)          // 4096
#define DA 96               // augmented attention dim (64 + 32)
#define CLUSTER 0.1f
#define LN_EPS 1e-6f

// ------------------- scratch (static device allocations) -------------------
__device__ float g_xln[BS*Dd];
__device__ float g_q  [BS*Dd];
__device__ float g_k  [BS*Dd];
__device__ float g_v  [BS*Dd];
__device__ float g_qb [BS*Hh*NBb];
__device__ float g_kb [BS*Hh*NBb];
__device__ float g_QA [(long)Bb*Hh*Ss*DA];
__device__ float g_KA [(long)Bb*Hh*Ss*DA];
__device__ float g_VT [(long)Bb*Hh*Ss*DHh];
__device__ float g_AO [BS*Dd];
__device__ float g_x1 [BS*Dd];
__device__ float g_yln[BS*Dd];
__device__ float g_h1 [(long)BS*MLPD];
__device__ float g_bsum[2*Hh*NBb];

// ------------------------------- LayerNorm ---------------------------------
__global__ void ln_kernel(const float* __restrict__ x, const float* __restrict__ g,
                          const float* __restrict__ bt, float* __restrict__ out)
{
    int row = blockIdx.x;
    int tid = threadIdx.x;                     // 256 threads, D/4 = 256 float4
    const float4* xr = (const float4*)(x + (long)row*Dd);
    float4 v = xr[tid];
    float s  = v.x+v.y+v.z+v.w;
    float s2 = v.x*v.x+v.y*v.y+v.z*v.z+v.w*v.w;
    __shared__ float sh[16];
    #pragma unroll
    for (int off=16; off; off>>=1) {
        s  += __shfl_xor_sync(0xffffffffu, s,  off);
        s2 += __shfl_xor_sync(0xffffffffu, s2, off);
    }
    int wid = tid >> 5;
    if ((tid & 31) == 0) { sh[wid] = s; sh[8+wid] = s2; }
    __syncthreads();
    if (tid < 32) {
        float a  = (tid < 8) ? sh[tid]   : 0.f;
        float b2 = (tid < 8) ? sh[8+tid] : 0.f;
        #pragma unroll
        for (int off=4; off; off>>=1) {
            a  += __shfl_xor_sync(0xffffffffu, a,  off);
            b2 += __shfl_xor_sync(0xffffffffu, b2, off);
        }
        if (tid == 0) { sh[0] = a; sh[1] = b2; }
    }
    __syncthreads();
    float mu  = sh[0] * (1.f/Dd);
    float var = sh[1] * (1.f/Dd) - mu*mu;
    float inv = rsqrtf(var + LN_EPS);
    float4 gg = ((const float4*)g)[tid];
    float4 bb = ((const float4*)bt)[tid];
    float4 r;
    r.x = (v.x-mu)*inv*gg.x + bb.x;
    r.y = (v.y-mu)*inv*gg.y + bb.y;
    r.z = (v.z-mu)*inv*gg.z + bb.z;
    r.w = (v.w-mu)*inv*gg.w + bb.w;
    ((float4*)(out + (long)row*Dd))[tid] = r;
}

// ------------------------------ fp32 GEMM 128x128x16 ------------------------
// C[M,N] = A[M,K] @ B[K,N] (+bias) (+relu) (+res)
__global__ __launch_bounds__(256, 2)
void gemm128(const float* __restrict__ A, const float* __restrict__ Bm,
             float* __restrict__ C, int M, int N, int K,
             const float* __restrict__ bias, const float* __restrict__ res, int relu)
{
    __shared__ float As[16][128];
    __shared__ float Bs[16][128];
    int tid = threadIdx.x;
    int ty = tid >> 4;          // 0..15 -> rows 8*ty
    int tx = tid & 15;          // 0..15 -> cols 8*tx
    int m0 = blockIdx.y * 128;
    int n0 = blockIdx.x * 128;

    float acc[8][8];
    #pragma unroll
    for (int i=0;i<8;i++)
        #pragma unroll
        for (int j=0;j<8;j++) acc[i][j] = 0.f;

    int arow = tid >> 1;         // 0..127
    int acol = (tid & 1) * 8;    // 0 or 8
    int brow = tid >> 4;         // 0..15
    int bcol = (tid & 15) * 8;
    const float* Aptr = A + (long)(m0+arow)*K + acol;
    const float* Bptr = Bm + (long)brow*N + n0 + bcol;

    for (int k0 = 0; k0 < K; k0 += 16) {
        float4 a0 = *(const float4*)(Aptr + k0);
        float4 a1 = *(const float4*)(Aptr + k0 + 4);
        As[acol+0][arow]=a0.x; As[acol+1][arow]=a0.y;
        As[acol+2][arow]=a0.z; As[acol+3][arow]=a0.w;
        As[acol+4][arow]=a1.x; As[acol+5][arow]=a1.y;
        As[acol+6][arow]=a1.z; As[acol+7][arow]=a1.w;
        const float* bp = Bptr + (long)k0*N;
        *(float4*)&Bs[brow][bcol]   = *(const float4*)bp;
        *(float4*)&Bs[brow][bcol+4] = *(const float4*)(bp+4);
        __syncthreads();
        #pragma unroll
        for (int k=0;k<16;k++) {
            float a[8], b[8];
            *(float4*)&a[0] = *(const float4*)&As[k][ty*8];
            *(float4*)&a[4] = *(const float4*)&As[k][ty*8+4];
            *(float4*)&b[0] = *(const float4*)&Bs[k][tx*8];
            *(float4*)&b[4] = *(const float4*)&Bs[k][tx*8+4];
            #pragma unroll
            for (int i=0;i<8;i++)
                #pragma unroll
                for (int j=0;j<8;j++) acc[i][j] += a[i]*b[j];
        }
        __syncthreads();
    }

    #pragma unroll
    for (int i=0;i<8;i++) {
        long row = m0 + ty*8 + i;
        #pragma unroll
        for (int j=0;j<8;j+=4) {
            int col = n0 + tx*8 + j;
            float4 v;
            v.x = acc[i][j]; v.y = acc[i][j+1]; v.z = acc[i][j+2]; v.w = acc[i][j+3];
            if (bias) {
                const float4 bv = *(const float4*)&bias[col];
                v.x += bv.x; v.y += bv.y; v.z += bv.z; v.w += bv.w;
            }
            if (relu) {
                v.x = fmaxf(v.x, 0.f); v.y = fmaxf(v.y, 0.f);
                v.z = fmaxf(v.z, 0.f); v.w = fmaxf(v.w, 0.f);
            }
            if (res) {
                const float4 rv = *(const float4*)&res[row*N + col];
                v.x += rv.x; v.y += rv.y; v.z += rv.z; v.w += rv.w;
            }
            *(float4*)&C[row*N + col] = v;
        }
    }
}

// ------------------------- bucket softmax (qb / kb) -------------------------
// one warp per (b,s,h); lane n in 0..31 computes logits[n] then softmax
__global__ void bucket_kernel(const float* __restrict__ qk, const float* __restrict__ Wh,
                              float* __restrict__ out)
{
    int gw   = blockIdx.x * (blockDim.x >> 5) + (threadIdx.x >> 5);
    int lane = threadIdx.x & 31;
    if (gw >= BS*Hh) return;
    int h  = gw % Hh;
    int bs = gw / Hh;
    const float* qrow = qk + (long)bs*Dd + h*DHh;
    const float* W    = Wh + (long)h*DHh*NBb;
    float acc = 0.f;
    #pragma unroll
    for (int f=0; f<DHh; f++) acc += qrow[f] * W[f*NBb + lane];
    float m = acc;
    #pragma unroll
    for (int off=16; off; off>>=1) m = fmaxf(m, __shfl_xor_sync(0xffffffffu, m, off));
    float e = __expf(acc - m);
    float s = e;
    #pragma unroll
    for (int off=16; off; off>>=1) s += __shfl_xor_sync(0xffffffffu, s, off);
    out[(long)gw*NBb + lane] = e / s;
}

// ------------------- build augmented QA/KA and transposed V -----------------
__global__ void augment_kernel(const float* __restrict__ q, const float* __restrict__ k,
                               const float* __restrict__ qb, const float* __restrict__ kb,
                               float* __restrict__ QA, float* __restrict__ KA)
{
    long i = (long)blockIdx.x * blockDim.x + threadIdx.x;
    const long total = (long)Bb*Hh*Ss*DA;
    if (i >= total) return;
    int  j  = (int)(i % DA);
    long r  = i / DA;
    int  s  = (int)(r % Ss);
    int  bh = (int)(r / Ss);
    int  h  = bh % Hh, b = bh / Hh;
    float qa, ka;
    if (j < DHh) {
        long base = ((long)(b*Ss + s))*Dd + h*DHh + j;
        qa = q[base] * 0.125f;           // 1/sqrt(64)
        ka = k[base];
    } else {
        long base = ((long)(b*Ss + s)*Hh + h)*NBb + (j - DHh);
        qa = CLUSTER * qb[base];
        ka = kb[base];
    }
    QA[i] = qa; KA[i] = ka;
}

__global__ void vtrans_kernel(const float* __restrict__ v, float* __restrict__ VT)
{
    long i = (long)blockIdx.x * blockDim.x + threadIdx.x;
    const long total = (long)Bb*Hh*Ss*DHh;
    if (i >= total) return;
    int  j  = (int)(i % DHh);
    long r  = i / DHh;
    int  s  = (int)(r % Ss);
    int  bh = (int)(r / Ss);
    int  h  = bh % Hh, b = bh / Hh;
    VT[i] = v[((long)(b*Ss + s))*Dd + h*DHh + j];
}

// ------------------------------ flash attention -----------------------------
#define BQ 64
#define BK 64
#define LDQ (BQ+4)   // 68: 16B-aligned rows, non-pathological banks

__global__ __launch_bounds__(256, 2)
void flash_kernel(const float* __restrict__ QA, const float* __restrict__ KA,
                  const float* __restrict__ VT, float* __restrict__ AO)
{
    extern __shared__ float sm[];
    float* qs = sm;                   // [DA][LDQ]
    float* ks = qs + DA*LDQ;          // [DA][LDQ]
    float* vs = ks + DA*LDQ;          // [BK][DHh]
    float* ps = vs + BK*DHh;          // [BQ][LDQ]

    const int tid = threadIdx.x;
    const int ty  = tid >> 4;         // 0..15 -> q rows 4*ty
    const int tx  = tid & 15;         // 0..15 -> cols 4*tx
    const int bh  = blockIdx.y;
    const int b   = bh / Hh, h = bh % Hh;
    const int q0  = blockIdx.x * BQ;

    const float* QAp = QA + ((long)bh*Ss + q0)*DA;
    const float* KAp = KA + (long)bh*Ss*DA;
    const float* VTp = VT + (long)bh*Ss*DHh;

    for (int i = tid; i < BQ*DA; i += 256) {
        int r = i / DA, d = i % DA;
        qs[d*LDQ + r] = QAp[(long)r*DA + d];
    }
    float m[4], l[4], o[4][4];
    #pragma unroll
    for (int i=0;i<4;i++){ m[i] = -1e30f; l[i] = 0.f;
        #pragma unroll
        for (int j=0;j<4;j++) o[i][j] = 0.f; }
    __syncthreads();

    for (int k0 = 0; k0 < Ss; k0 += BK) {
        for (int i = tid; i < BK*DA; i += 256) {
            int r = i / DA, d = i % DA;
            ks[d*LDQ + r] = KAp[(long)(k0+r)*DA + d];
        }
        for (int i = tid; i < BK*DHh; i += 256)
            vs[i] = VTp[(long)k0*DHh + i];
        __syncthreads();

        float s[4][4];
        #pragma unroll
        for (int i=0;i<4;i++)
            #pragma unroll
            for (int j=0;j<4;j++) s[i][j] = 0.f;

        #pragma unroll 4
        for (int d=0; d<DA; d++) {
            float4 a  = *(const float4*)&qs[d*LDQ + ty*4];
            float4 bb = *(const float4*)&ks[d*LDQ + tx*4];
            s[0][0]+=a.x*bb.x; s[0][1]+=a.x*bb.y; s[0][2]+=a.x*bb.z; s[0][3]+=a.x*bb.w;
            s[1][0]+=a.y*bb.x; s[1][1]+=a.y*bb.y; s[1][2]+=a.y*bb.z; s[1][3]+=a.y*bb.w;
            s[2][0]+=a.z*bb.x; s[2][1]+=a.z*bb.y; s[2][2]+=a.z*bb.z; s[2][3]+=a.z*bb.w;
            s[3][0]+=a.w*bb.x; s[3][1]+=a.w*bb.y; s[3][2]+=a.w*bb.z; s[3][3]+=a.w*bb.w;
        }

        #pragma unroll
        for (int i=0;i<4;i++) {
            float rm = fmaxf(fmaxf(s[i][0],s[i][1]), fmaxf(s[i][2],s[i][3]));
            #pragma unroll
            for (int off=8; off; off>>=1)
                rm = fmaxf(rm, __shfl_xor_sync(0xffffffffu, rm, off, 16));
            float mn = fmaxf(m[i], rm);
            float alpha = __expf(m[i] - mn);
            m[i] = mn;
            float rs = 0.f;
            #pragma unroll
            for (int j=0;j<4;j++) { float p = __expf(s[i][j]-mn); s[i][j]=p; rs += p; }
            #pragma unroll
            for (int off=8; off; off>>=1)
                rs += __shfl_xor_sync(0xffffffffu, rs, off, 16);
            l[i] = l[i]*alpha + rs;
            #pragma unroll
            for (int j=0;j<4;j++) o[i][j] *= alpha;
            *(float4*)&ps[(ty*4+i)*LDQ + tx*4] = make_float4(s[i][0],s[i][1],s[i][2],s[i][3]);
        }
        __syncthreads();

        #pragma unroll 4
        for (int kk=0; kk<BK; kk++) {
            float4 vv = *(const float4*)&vs[kk*DHh + tx*4];
            #pragma unroll
            for (int i=0;i<4;i++) {
                float p = ps[(ty*4+i)*LDQ + kk];
                o[i][0] += p*vv.x; o[i][1] += p*vv.y;
                o[i][2] += p*vv.z; o[i][3] += p*vv.w;
            }
        }
        __syncthreads();
    }

    #pragma unroll
    for (int i=0;i<4;i++) {
        float inv = 1.f / l[i];
        long srow = q0 + ty*4 + i;
        float4 w = make_float4(o[i][0]*inv, o[i][1]*inv, o[i][2]*inv, o[i][3]*inv);
        *(float4*)&AO[((long)b*Ss + srow)*Dd + h*DHh + tx*4] = w;
    }
}

// ---------------------------- bucket load-balance loss ----------------------
__global__ void bsum_kernel(const float* __restrict__ qb, const float* __restrict__ kb,
                            float* __restrict__ bsum)
{
    int id = blockIdx.x;                    // 0..2*H*NB-1
    const float* src = (id < Hh*NBb) ? qb : kb;
    int hn = id % (Hh*NBb);
    float s = 0.f;
    for (int r = threadIdx.x; r < BS; r += blockDim.x)
        s += src[(long)r*(Hh*NBb) + hn];
    __shared__ float sh[8];
    #pragma unroll
    for (int off=16; off; off>>=1) s += __shfl_xor_sync(0xffffffffu, s, off);
    int wid = threadIdx.x >> 5;
    if ((threadIdx.x & 31) == 0) sh[wid] = s;
    __syncthreads();
    if (threadIdx.x < 8) {
        float a = sh[threadIdx.x];
        #pragma unroll
        for (int off=4; off; off>>=1) a += __shfl_xor_sync(0xffffffffu, a, off, 8);
        if (threadIdx.x == 0) bsum[id] = a / (float)BS;
    }
}

__global__ void loss_kernel(const float* __restrict__ bsum, float* __restrict__ out)
{
    float t = 0.f;
    for (int i = threadIdx.x; i < 2*Hh*NBb; i += blockDim.x) {
        float v = bsum[i]; t += v*v;
    }
    __shared__ float sh[8];
    #pragma unroll
    for (int off=16; off; off>>=1) t += __shfl_xor_sync(0xffffffffu, t, off);
    int wid = threadIdx.x >> 5;
    if ((threadIdx.x & 31) == 0) sh[wid] = t;
    __syncthreads();
    if (threadIdx.x == 0) {
        float tot = 0.f;
        for (int i=0;i<8;i++) tot += sh[i];
        out[(long)BS*Dd] = 0.5f * (float)NBb / (float)Hh * tot;
    }
}

// --------------------------------- launch -----------------------------------
extern "C" void kernel_launch(void* const* d_in, const int* in_sizes, int n_in,
                              void* d_out, int out_size)
{
    const float* inputs = (const float*)d_in[0];
    const float* ln1_g  = (const float*)d_in[1];
    const float* ln1_b  = (const float*)d_in[2];
    const float* Wq     = (const float*)d_in[3];
    const float* Wk     = (const float*)d_in[4];
    const float* Wv     = (const float*)d_in[5];
    const float* Whq    = (const float*)d_in[6];
    const float* Whk    = (const float*)d_in[7];
    const float* Wo     = (const float*)d_in[8];
    const float* ln2_g  = (const float*)d_in[9];
    const float* ln2_b  = (const float*)d_in[10];
    const float* W1     = (const float*)d_in[11];
    const float* b1     = (const float*)d_in[12];
    const float* W2     = (const float*)d_in[13];
    const float* b2     = (const float*)d_in[14];
    float* out = (float*)d_out;

    float *xln, *q, *k, *v, *qb, *kb, *QA, *KA, *VT, *AO, *x1, *yln, *h1, *bsum;
    cudaGetSymbolAddress((void**)&xln, g_xln);
    cudaGetSymbolAddress((void**)&q,   g_q);
    cudaGetSymbolAddress((void**)&k,   g_k);
    cudaGetSymbolAddress((void**)&v,   g_v);
    cudaGetSymbolAddress((void**)&qb,  g_qb);
    cudaGetSymbolAddress((void**)&kb,  g_kb);
    cudaGetSymbolAddress((void**)&QA,  g_QA);
    cudaGetSymbolAddress((void**)&KA,  g_KA);
    cudaGetSymbolAddress((void**)&VT,  g_VT);
    cudaGetSymbolAddress((void**)&AO,  g_AO);
    cudaGetSymbolAddress((void**)&x1,  g_x1);
    cudaGetSymbolAddress((void**)&yln, g_yln);
    cudaGetSymbolAddress((void**)&h1,  g_h1);
    cudaGetSymbolAddress((void**)&bsum,g_bsum);

    // 1. LN1
    ln_kernel<<<BS, 256>>>(inputs, ln1_g, ln1_b, xln);

    // 2. QKV projections
    dim3 gqkv(Dd/128, BS/128);
    gemm128<<<gqkv, 256>>>(xln, Wq, q, BS, Dd, Dd, nullptr, nullptr, 0);
    gemm128<<<gqkv, 256>>>(xln, Wk, k, BS, Dd, Dd, nullptr, nullptr, 0);
    gemm128<<<gqkv, 256>>>(xln, Wv, v, BS, Dd, Dd, nullptr, nullptr, 0);

    // 3. bucket softmaxes
    int nwarp_blocks = (BS*Hh) / 8;     // 8 warps per block
    bucket_kernel<<<nwarp_blocks, 256>>>(q, Whq, qb);
    bucket_kernel<<<nwarp_blocks, 256>>>(k, Whk, kb);

    // 4. augmented Q/K and transposed V
    {
        long totA = (long)Bb*Hh*Ss*DA;
        augment_kernel<<<(int)((totA + 255)/256), 256>>>(q, k, qb, kb, QA, KA);
        long totV = (long)Bb*Hh*Ss*DHh;
        vtrans_kernel<<<(int)((totV + 255)/256), 256>>>(v, VT);
    }

    // 5. flash attention over augmented dim
    {
        int smem = (DA*LDQ*2 + BK*DHh + BQ*LDQ) * (int)sizeof(float);  // 86016
        cudaFuncSetAttribute(flash_kernel, cudaFuncAttributeMaxDynamicSharedMemorySize, smem);
        dim3 gf(Ss/BQ, Bb*Hh);
        flash_kernel<<<gf, 256, smem>>>(QA, KA, VT, AO);
    }

    // 6. output projection + residual -> x1
    gemm128<<<gqkv, 256>>>(AO, Wo, x1, BS, Dd, Dd, nullptr, inputs, 0);

    // 7. LN2
    ln_kernel<<<BS, 256>>>(x1, ln2_g, ln2_b, yln);

    // 8. MLP up + bias + relu
    dim3 g1(MLPD/128, BS/128);
    gemm128<<<g1, 256>>>(yln, W1, h1, BS, MLPD, Dd, b1, nullptr, 1);

    // 9. MLP down + bias + residual -> d_out[0 .. BS*D)
    dim3 g2(Dd/128, BS/128);
    gemm128<<<g2, 256>>>(h1, W2, out, BS, Dd, MLPD, b2, x1, 0);

    // 10/11. auxiliary bucket loss -> d_out[BS*D]
    bsum_kernel<<<2*Hh*NBb, 256>>>(qb, kb, bsum);
    loss_kernel<<<1, 256>>>(bsum, out);
}

// round 5
// speedup vs baseline: 1.5089x; 1.5089x over previous
#include <cuda_runtime.h>
#include <cuda_bf16.h>
#include <cstdint>

#define Bb 2
#define Ss 2048
#define Dd 1024
#define Hh 16
#define DHh 64
#define NBb 32
#define MLPD 4096
#define BS (Bb*Ss)          // 4096
#define DA 96               // augmented attention dim (64 + 32)
#define CLUSTER 0.1f
#define LN_EPS 1e-6f

// ===================== helpers =============================================
__device__ __forceinline__ uint32_t smem_u32(const void* p) {
    uint32_t a;
    asm("{ .reg .u64 t; cvta.to.shared.u64 t, %1; cvt.u32.u64 %0, t; }" : "=r"(a) : "l"(p));
    return a;
}
#define LDSM_X4(r, addr) \
    asm volatile("ldmatrix.sync.aligned.m8n8.x4.shared.b16 {%0,%1,%2,%3}, [%4];" \
        : "=r"((r)[0]), "=r"((r)[1]), "=r"((r)[2]), "=r"((r)[3]) : "r"(addr))
#define LDSM_X4T(r, addr) \
    asm volatile("ldmatrix.sync.aligned.m8n8.x4.trans.shared.b16 {%0,%1,%2,%3}, [%4];" \
        : "=r"((r)[0]), "=r"((r)[1]), "=r"((r)[2]), "=r"((r)[3]) : "r"(addr))
#define MMA_BF16(c, a, b0, b1) \
    asm volatile("mma.sync.aligned.m16n8k16.row.col.f32.bf16.bf16.f32 " \
        "{%0,%1,%2,%3}, {%4,%5,%6,%7}, {%8,%9}, {%0,%1,%2,%3};" \
        : "+f"((c)[0]), "+f"((c)[1]), "+f"((c)[2]), "+f"((c)[3]) \
        : "r"((a)[0]), "r"((a)[1]), "r"((a)[2]), "r"((a)[3]), "r"(b0), "r"(b1))

// ------------------- scratch (static device allocations) -------------------
__device__ float g_xln[BS*Dd];
__device__ float g_q  [BS*Dd];
__device__ float g_k  [BS*Dd];
__device__ float g_v  [BS*Dd];
__device__ float g_qb [BS*Hh*NBb];
__device__ float g_kb [BS*Hh*NBb];
__device__ float g_QA [(long)Bb*Hh*Ss*DA];
__device__ float g_KA [(long)Bb*Hh*Ss*DA];
__device__ float g_VT [(long)Bb*Hh*Ss*DHh];
__device__ float g_AO [BS*Dd];
__device__ float g_x1 [BS*Dd];
__device__ float g_yln[BS*Dd];
__device__ float g_h1 [(long)BS*MLPD];
__device__ float g_bsum[2*Hh*NBb];

// ------------------------------- LayerNorm ---------------------------------
__global__ void ln_kernel(const float* __restrict__ x, const float* __restrict__ g,
                          const float* __restrict__ bt, float* __restrict__ out)
{
    int row = blockIdx.x;
    int tid = threadIdx.x;                     // 256 threads, D/4 = 256 float4
    const float4* xr = (const float4*)(x + (long)row*Dd);
    float4 v = xr[tid];
    float s  = v.x+v.y+v.z+v.w;
    float s2 = v.x*v.x+v.y*v.y+v.z*v.z+v.w*v.w;
    __shared__ float sh[16];
    #pragma unroll
    for (int off=16; off; off>>=1) {
        s  += __shfl_xor_sync(0xffffffffu, s,  off);
        s2 += __shfl_xor_sync(0xffffffffu, s2, off);
    }
    int wid = tid >> 5;
    if ((tid & 31) == 0) { sh[wid] = s; sh[8+wid] = s2; }
    __syncthreads();
    if (tid < 32) {
        float a  = (tid < 8) ? sh[tid]   : 0.f;
        float b2 = (tid < 8) ? sh[8+tid] : 0.f;
        #pragma unroll
        for (int off=4; off; off>>=1) {
            a  += __shfl_xor_sync(0xffffffffu, a,  off);
            b2 += __shfl_xor_sync(0xffffffffu, b2, off);
        }
        if (tid == 0) { sh[0] = a; sh[1] = b2; }
    }
    __syncthreads();
    float mu  = sh[0] * (1.f/Dd);
    float var = sh[1] * (1.f/Dd) - mu*mu;
    float inv = rsqrtf(var + LN_EPS);
    float4 gg = ((const float4*)g)[tid];
    float4 bb = ((const float4*)bt)[tid];
    float4 r;
    r.x = (v.x-mu)*inv*gg.x + bb.x;
    r.y = (v.y-mu)*inv*gg.y + bb.y;
    r.z = (v.z-mu)*inv*gg.z + bb.z;
    r.w = (v.w-mu)*inv*gg.w + bb.w;
    ((float4*)(out + (long)row*Dd))[tid] = r;
}

// ==================== bf16x3 mma.sync GEMM =================================
// C[M,N] = A[M,K] @ B[K,N] (+bias) (+relu) (+res)
// A row-major, B row-major; 128x128 tile, K-chunk 32, double-buffered.
#define SWA 40      // A smem row stride (halfs): 80B, conflict-free LDSM
#define SWB 136     // B smem row stride (halfs): 272B, conflict-free LDSM-trans
#define ASTG (128*SWA)      // 5120 halfs / plane / stage
#define BSTG (32*SWB)       // 4352 halfs / plane / stage
#define GEMM_SMEM ((2*ASTG*2 + 2*BSTG*2) * 2)   // bytes = 75776

__device__ __forceinline__ void split_sts(const float* p,
                                          __nv_bfloat16* hiDst, __nv_bfloat16* loDst)
{
    __align__(16) __nv_bfloat16 hh[16], ll[16];
    #pragma unroll
    for (int i = 0; i < 16; i++) {
        float x = p[i];
        __nv_bfloat16 h = __float2bfloat16_rn(x);
        hh[i] = h;
        ll[i] = __float2bfloat16_rn(x - __bfloat162float(h));
    }
    ((uint4*)hiDst)[0] = ((uint4*)hh)[0];
    ((uint4*)hiDst)[1] = ((uint4*)hh)[1];
    ((uint4*)loDst)[0] = ((uint4*)ll)[0];
    ((uint4*)loDst)[1] = ((uint4*)ll)[1];
}

__global__ __launch_bounds__(256, 1)
void gemm_mma(const float* __restrict__ A, const float* __restrict__ Bw,
              float* __restrict__ C, int M, int N, int K,
              const float* __restrict__ bias, const float* __restrict__ res, int relu)
{
    extern __shared__ __nv_bfloat16 smh[];
    __nv_bfloat16* sAh = smh;                 // [2][ASTG]
    __nv_bfloat16* sAl = smh + 2*ASTG;        // [2][ASTG]
    __nv_bfloat16* sBh = smh + 4*ASTG;        // [2][BSTG]
    __nv_bfloat16* sBl = smh + 4*ASTG + 2*BSTG;
    const uint32_t smbase = smem_u32(smh);

    const int tid  = threadIdx.x;
    const int lane = tid & 31;
    const int wid  = tid >> 5;
    const int m0 = blockIdx.y * 128, n0 = blockIdx.x * 128;
    const int m0w = (wid & 3) * 32, n0w = (wid >> 2) * 64;

    // producer mapping
    const int arow = tid >> 1, akh = (tid & 1) * 16;      // A: 128 rows x 2 halves
    const int bkr  = tid >> 3, bns = (tid & 7) * 16;      // B: 32 k-rows x 8 segs
    const float* Ag0 = A  + (long)(m0 + arow)*K + akh;
    const float* Bg0 = Bw + (long)bkr*N + n0 + bns;

    float acc[2][8][4];
    #pragma unroll
    for (int i=0;i<2;i++)
        #pragma unroll
        for (int j=0;j<8;j++)
            #pragma unroll
            for (int t=0;t<4;t++) acc[i][j][t] = 0.f;

    const int KC = K >> 5;
    float pa[16], pb[16];

    // chunk 0
    #pragma unroll
    for (int i=0;i<4;i++) *(float4*)&pa[i*4] = *(const float4*)(Ag0 + i*4);
    #pragma unroll
    for (int i=0;i<4;i++) *(float4*)&pb[i*4] = *(const float4*)(Bg0 + i*4);
    split_sts(pa, sAh + arow*SWA + akh, sAl + arow*SWA + akh);
    split_sts(pb, sBh + bkr*SWB + bns, sBl + bkr*SWB + bns);
    __syncthreads();

    // ldmatrix lane mapping (constant per thread)
    const int arow_l = m0w + (lane & 15);
    const int acol_l = (lane >> 4) << 3;
    const int bkr_l  = ((lane >> 3) & 1) * 8 + (lane & 7);
    const int bnc_l  = n0w + ((lane >> 4) << 3);

    for (int c = 0; c < KC; c++) {
        const int st = c & 1;
        if (c + 1 < KC) {
            const float* Agn = Ag0 + (c+1)*32;
            const float* Bgn = Bg0 + (long)(c+1)*32*N;
            #pragma unroll
            for (int i=0;i<4;i++) *(float4*)&pa[i*4] = *(const float4*)(Agn + i*4);
            #pragma unroll
            for (int i=0;i<4;i++) *(float4*)&pb[i*4] = *(const float4*)(Bgn + i*4);
        }

        const uint32_t baseAh = smbase + (uint32_t)(st*ASTG)*2;
        const uint32_t baseAl = baseAh + (uint32_t)(2*ASTG)*2;
        const uint32_t baseBh = smbase + (uint32_t)(4*ASTG + st*BSTG)*2;
        const uint32_t baseBl = baseBh + (uint32_t)(2*BSTG)*2;

        #pragma unroll
        for (int ks = 0; ks < 2; ks++) {
            const int kst = ks*16;
            uint32_t ah[2][4], al[2][4];
            {
                uint32_t a0 = baseAh + (uint32_t)(arow_l*SWA + kst + acol_l)*2;
                LDSM_X4(ah[0], a0);
                LDSM_X4(ah[1], a0 + 16*SWA*2);
                uint32_t a1 = baseAl + (uint32_t)(arow_l*SWA + kst + acol_l)*2;
                LDSM_X4(al[0], a1);
                LDSM_X4(al[1], a1 + 16*SWA*2);
            }
            #pragma unroll
            for (int ntp = 0; ntp < 4; ntp++) {
                uint32_t bh[4], bl[4];
                uint32_t boff = (uint32_t)((kst + bkr_l)*SWB + bnc_l + ntp*16)*2;
                LDSM_X4T(bh, baseBh + boff);
                LDSM_X4T(bl, baseBl + boff);
                #pragma unroll
                for (int mt = 0; mt < 2; mt++) {
                    MMA_BF16(acc[mt][2*ntp],   ah[mt], bh[0], bh[1]);
                    MMA_BF16(acc[mt][2*ntp],   ah[mt], bl[0], bl[1]);
                    MMA_BF16(acc[mt][2*ntp],   al[mt], bh[0], bh[1]);
                    MMA_BF16(acc[mt][2*ntp+1], ah[mt], bh[2], bh[3]);
                    MMA_BF16(acc[mt][2*ntp+1], ah[mt], bl[2], bl[3]);
                    MMA_BF16(acc[mt][2*ntp+1], al[mt], bh[2], bh[3]);
                }
            }
        }

        if (c + 1 < KC) {
            const int s2 = st ^ 1;
            split_sts(pa, sAh + s2*ASTG + arow*SWA + akh, sAl + s2*ASTG + arow*SWA + akh);
            split_sts(pb, sBh + s2*BSTG + bkr*SWB + bns, sBl + s2*BSTG + bkr*SWB + bns);
        }
        __syncthreads();
    }

    // epilogue
    const int gid = lane >> 2, tig = lane & 3;
    #pragma unroll
    for (int mt = 0; mt < 2; mt++) {
        #pragma unroll
        for (int nt = 0; nt < 8; nt++) {
            long row = m0 + m0w + mt*16 + gid;
            int  col = n0 + n0w + nt*8 + tig*2;
            float2 v0 = make_float2(acc[mt][nt][0], acc[mt][nt][1]);
            float2 v1 = make_float2(acc[mt][nt][2], acc[mt][nt][3]);
            if (bias) {
                float2 bv = *(const float2*)&bias[col];
                v0.x += bv.x; v0.y += bv.y; v1.x += bv.x; v1.y += bv.y;
            }
            if (relu) {
                v0.x = fmaxf(v0.x, 0.f); v0.y = fmaxf(v0.y, 0.f);
                v1.x = fmaxf(v1.x, 0.f); v1.y = fmaxf(v1.y, 0.f);
            }
            if (res) {
                float2 r0 = *(const float2*)&res[row*N + col];
                float2 r1 = *(const float2*)&res[(row+8)*N + col];
                v0.x += r0.x; v0.y += r0.y; v1.x += r1.x; v1.y += r1.y;
            }
            *(float2*)&C[row*N + col]     = v0;
            *(float2*)&C[(row+8)*N + col] = v1;
        }
    }
}

// ------------------------- bucket softmax (qb / kb) -------------------------
__global__ void bucket_kernel(const float* __restrict__ qk, const float* __restrict__ Wh,
                              float* __restrict__ out)
{
    int gw   = blockIdx.x * (blockDim.x >> 5) + (threadIdx.x >> 5);
    int lane = threadIdx.x & 31;
    if (gw >= BS*Hh) return;
    int h  = gw % Hh;
    int bs = gw / Hh;
    const float* qrow = qk + (long)bs*Dd + h*DHh;
    const float* W    = Wh + (long)h*DHh*NBb;
    float acc = 0.f;
    #pragma unroll
    for (int f=0; f<DHh; f++) acc += qrow[f] * W[f*NBb + lane];
    float m = acc;
    #pragma unroll
    for (int off=16; off; off>>=1) m = fmaxf(m, __shfl_xor_sync(0xffffffffu, m, off));
    float e = __expf(acc - m);
    float s = e;
    #pragma unroll
    for (int off=16; off; off>>=1) s += __shfl_xor_sync(0xffffffffu, s, off);
    out[(long)gw*NBb + lane] = e / s;
}

// ------------------- build augmented QA/KA and transposed V -----------------
__global__ void augment_kernel(const float* __restrict__ q, const float* __restrict__ k,
                               const float* __restrict__ qb, const float* __restrict__ kb,
                               float* __restrict__ QA, float* __restrict__ KA)
{
    long i = (long)blockIdx.x * blockDim.x + threadIdx.x;
    const long total = (long)Bb*Hh*Ss*DA;
    if (i >= total) return;
    int  j  = (int)(i % DA);
    long r  = i / DA;
    int  s  = (int)(r % Ss);
    int  bh = (int)(r / Ss);
    int  h  = bh % Hh, b = bh / Hh;
    float qa, ka;
    if (j < DHh) {
        long base = ((long)(b*Ss + s))*Dd + h*DHh + j;
        qa = q[base] * 0.125f;           // 1/sqrt(64)
        ka = k[base];
    } else {
        long base = ((long)(b*Ss + s)*Hh + h)*NBb + (j - DHh);
        qa = CLUSTER * qb[base];
        ka = kb[base];
    }
    QA[i] = qa; KA[i] = ka;
}

__global__ void vtrans_kernel(const float* __restrict__ v, float* __restrict__ VT)
{
    long i = (long)blockIdx.x * blockDim.x + threadIdx.x;
    const long total = (long)Bb*Hh*Ss*DHh;
    if (i >= total) return;
    int  j  = (int)(i % DHh);
    long r  = i / DHh;
    int  s  = (int)(r % Ss);
    int  bh = (int)(r / Ss);
    int  h  = bh % Hh, b = bh / Hh;
    VT[i] = v[((long)(b*Ss + s))*Dd + h*DHh + j];
}

// ------------------------------ flash attention -----------------------------
#define BQ 64
#define BK 64
#define LDQ (BQ+4)   // 68: 16B-aligned rows, non-pathological banks

__global__ __launch_bounds__(256, 2)
void flash_kernel(const float* __restrict__ QA, const float* __restrict__ KA,
                  const float* __restrict__ VT, float* __restrict__ AO)
{
    extern __shared__ float sm[];
    float* qs = sm;                   // [DA][LDQ]
    float* ks = qs + DA*LDQ;          // [DA][LDQ]
    float* vs = ks + DA*LDQ;          // [BK][DHh]
    float* ps = vs + BK*DHh;          // [BQ][LDQ]

    const int tid = threadIdx.x;
    const int ty  = tid >> 4;         // 0..15 -> q rows 4*ty
    const int tx  = tid & 15;         // 0..15 -> cols 4*tx
    const int bh  = blockIdx.y;
    const int b   = bh / Hh, h = bh % Hh;
    const int q0  = blockIdx.x * BQ;

    const float* QAp = QA + ((long)bh*Ss + q0)*DA;
    const float* KAp = KA + (long)bh*Ss*DA;
    const float* VTp = VT + (long)bh*Ss*DHh;

    for (int i = tid; i < BQ*DA; i += 256) {
        int r = i / DA, d = i % DA;
        qs[d*LDQ + r] = QAp[(long)r*DA + d];
    }
    float m[4], l[4], o[4][4];
    #pragma unroll
    for (int i=0;i<4;i++){ m[i] = -1e30f; l[i] = 0.f;
        #pragma unroll
        for (int j=0;j<4;j++) o[i][j] = 0.f; }
    __syncthreads();

    for (int k0 = 0; k0 < Ss; k0 += BK) {
        for (int i = tid; i < BK*DA; i += 256) {
            int r = i / DA, d = i % DA;
            ks[d*LDQ + r] = KAp[(long)(k0+r)*DA + d];
        }
        for (int i = tid; i < BK*DHh; i += 256)
            vs[i] = VTp[(long)k0*DHh + i];
        __syncthreads();

        float s[4][4];
        #pragma unroll
        for (int i=0;i<4;i++)
            #pragma unroll
            for (int j=0;j<4;j++) s[i][j] = 0.f;

        #pragma unroll 4
        for (int d=0; d<DA; d++) {
            float4 a  = *(const float4*)&qs[d*LDQ + ty*4];
            float4 bb = *(const float4*)&ks[d*LDQ + tx*4];
            s[0][0]+=a.x*bb.x; s[0][1]+=a.x*bb.y; s[0][2]+=a.x*bb.z; s[0][3]+=a.x*bb.w;
            s[1][0]+=a.y*bb.x; s[1][1]+=a.y*bb.y; s[1][2]+=a.y*bb.z; s[1][3]+=a.y*bb.w;
            s[2][0]+=a.z*bb.x; s[2][1]+=a.z*bb.y; s[2][2]+=a.z*bb.z; s[2][3]+=a.z*bb.w;
            s[3][0]+=a.w*bb.x; s[3][1]+=a.w*bb.y; s[3][2]+=a.w*bb.z; s[3][3]+=a.w*bb.w;
        }

        #pragma unroll
        for (int i=0;i<4;i++) {
            float rm = fmaxf(fmaxf(s[i][0],s[i][1]), fmaxf(s[i][2],s[i][3]));
            #pragma unroll
            for (int off=8; off; off>>=1)
                rm = fmaxf(rm, __shfl_xor_sync(0xffffffffu, rm, off, 16));
            float mn = fmaxf(m[i], rm);
            float alpha = __expf(m[i] - mn);
            m[i] = mn;
            float rs = 0.f;
            #pragma unroll
            for (int j=0;j<4;j++) { float p = __expf(s[i][j]-mn); s[i][j]=p; rs += p; }
            #pragma unroll
            for (int off=8; off; off>>=1)
                rs += __shfl_xor_sync(0xffffffffu, rs, off, 16);
            l[i] = l[i]*alpha + rs;
            #pragma unroll
            for (int j=0;j<4;j++) o[i][j] *= alpha;
            *(float4*)&ps[(ty*4+i)*LDQ + tx*4] = make_float4(s[i][0],s[i][1],s[i][2],s[i][3]);
        }
        __syncthreads();

        #pragma unroll 4
        for (int kk=0; kk<BK; kk++) {
            float4 vv = *(const float4*)&vs[kk*DHh + tx*4];
            #pragma unroll
            for (int i=0;i<4;i++) {
                float p = ps[(ty*4+i)*LDQ + kk];
                o[i][0] += p*vv.x; o[i][1] += p*vv.y;
                o[i][2] += p*vv.z; o[i][3] += p*vv.w;
            }
        }
        __syncthreads();
    }

    #pragma unroll
    for (int i=0;i<4;i++) {
        float inv = 1.f / l[i];
        long srow = q0 + ty*4 + i;
        float4 w = make_float4(o[i][0]*inv, o[i][1]*inv, o[i][2]*inv, o[i][3]*inv);
        *(float4*)&AO[((long)b*Ss + srow)*Dd + h*DHh + tx*4] = w;
    }
}

// ---------------------------- bucket load-balance loss ----------------------
__global__ void bsum_kernel(const float* __restrict__ qb, const float* __restrict__ kb,
                            float* __restrict__ bsum)
{
    int id = blockIdx.x;                    // 0..2*H*NB-1
    const float* src = (id < Hh*NBb) ? qb : kb;
    int hn = id % (Hh*NBb);
    float s = 0.f;
    for (int r = threadIdx.x; r < BS; r += blockDim.x)
        s += src[(long)r*(Hh*NBb) + hn];
    __shared__ float sh[8];
    #pragma unroll
    for (int off=16; off; off>>=1) s += __shfl_xor_sync(0xffffffffu, s, off);
    int wid = threadIdx.x >> 5;
    if ((threadIdx.x & 31) == 0) sh[wid] = s;
    __syncthreads();
    if (threadIdx.x < 8) {
        float a = sh[threadIdx.x];
        #pragma unroll
        for (int off=4; off; off>>=1) a += __shfl_xor_sync(0xffffffffu, a, off, 8);
        if (threadIdx.x == 0) bsum[id] = a / (float)BS;
    }
}

__global__ void loss_kernel(const float* __restrict__ bsum, float* __restrict__ out)
{
    float t = 0.f;
    for (int i = threadIdx.x; i < 2*Hh*NBb; i += blockDim.x) {
        float v = bsum[i]; t += v*v;
    }
    __shared__ float sh[8];
    #pragma unroll
    for (int off=16; off; off>>=1) t += __shfl_xor_sync(0xffffffffu, t, off);
    int wid = threadIdx.x >> 5;
    if ((threadIdx.x & 31) == 0) sh[wid] = t;
    __syncthreads();
    if (threadIdx.x == 0) {
        float tot = 0.f;
        for (int i=0;i<8;i++) tot += sh[i];
        out[(long)BS*Dd] = 0.5f * (float)NBb / (float)Hh * tot;
    }
}

// --------------------------------- launch -----------------------------------
extern "C" void kernel_launch(void* const* d_in, const int* in_sizes, int n_in,
                              void* d_out, int out_size)
{
    const float* inputs = (const float*)d_in[0];
    const float* ln1_g  = (const float*)d_in[1];
    const float* ln1_b  = (const float*)d_in[2];
    const float* Wq     = (const float*)d_in[3];
    const float* Wk     = (const float*)d_in[4];
    const float* Wv     = (const float*)d_in[5];
    const float* Whq    = (const float*)d_in[6];
    const float* Whk    = (const float*)d_in[7];
    const float* Wo     = (const float*)d_in[8];
    const float* ln2_g  = (const float*)d_in[9];
    const float* ln2_b  = (const float*)d_in[10];
    const float* W1     = (const float*)d_in[11];
    const float* b1     = (const float*)d_in[12];
    const float* W2     = (const float*)d_in[13];
    const float* b2     = (const float*)d_in[14];
    float* out = (float*)d_out;

    float *xln, *q, *k, *v, *qb, *kb, *QA, *KA, *VT, *AO, *x1, *yln, *h1, *bsum;
    cudaGetSymbolAddress((void**)&xln, g_xln);
    cudaGetSymbolAddress((void**)&q,   g_q);
    cudaGetSymbolAddress((void**)&k,   g_k);
    cudaGetSymbolAddress((void**)&v,   g_v);
    cudaGetSymbolAddress((void**)&qb,  g_qb);
    cudaGetSymbolAddress((void**)&kb,  g_kb);
    cudaGetSymbolAddress((void**)&QA,  g_QA);
    cudaGetSymbolAddress((void**)&KA,  g_KA);
    cudaGetSymbolAddress((void**)&VT,  g_VT);
    cudaGetSymbolAddress((void**)&AO,  g_AO);
    cudaGetSymbolAddress((void**)&x1,  g_x1);
    cudaGetSymbolAddress((void**)&yln, g_yln);
    cudaGetSymbolAddress((void**)&h1,  g_h1);
    cudaGetSymbolAddress((void**)&bsum,g_bsum);

    cudaFuncSetAttribute(gemm_mma, cudaFuncAttributeMaxDynamicSharedMemorySize, GEMM_SMEM);

    // 1. LN1
    ln_kernel<<<BS, 256>>>(inputs, ln1_g, ln1_b, xln);

    // 2. QKV projections (tensor cores via mma.sync, bf16x3)
    dim3 gqkv(Dd/128, BS/128);
    gemm_mma<<<gqkv, 256, GEMM_SMEM>>>(xln, Wq, q, BS, Dd, Dd, nullptr, nullptr, 0);
    gemm_mma<<<gqkv, 256, GEMM_SMEM>>>(xln, Wk, k, BS, Dd, Dd, nullptr, nullptr, 0);
    gemm_mma<<<gqkv, 256, GEMM_SMEM>>>(xln, Wv, v, BS, Dd, Dd, nullptr, nullptr, 0);

    // 3. bucket softmaxes
    int nwarp_blocks = (BS*Hh) / 8;     // 8 warps per block
    bucket_kernel<<<nwarp_blocks, 256>>>(q, Whq, qb);
    bucket_kernel<<<nwarp_blocks, 256>>>(k, Whk, kb);

    // 4. augmented Q/K and transposed V
    {
        long totA = (long)Bb*Hh*Ss*DA;
        augment_kernel<<<(int)((totA + 255)/256), 256>>>(q, k, qb, kb, QA, KA);
        long totV = (long)Bb*Hh*Ss*DHh;
        vtrans_kernel<<<(int)((totV + 255)/256), 256>>>(v, VT);
    }

    // 5. flash attention over augmented dim
    {
        int smem = (DA*LDQ*2 + BK*DHh + BQ*LDQ) * (int)sizeof(float);  // 86016
        cudaFuncSetAttribute(flash_kernel, cudaFuncAttributeMaxDynamicSharedMemorySize, smem);
        dim3 gf(Ss/BQ, Bb*Hh);
        flash_kernel<<<gf, 256, smem>>>(QA, KA, VT, AO);
    }

    // 6. output projection + residual -> x1
    gemm_mma<<<gqkv, 256, GEMM_SMEM>>>(AO, Wo, x1, BS, Dd, Dd, nullptr, inputs, 0);

    // 7. LN2
    ln_kernel<<<BS, 256>>>(x1, ln2_g, ln2_b, yln);

    // 8. MLP up + bias + relu
    dim3 g1(MLPD/128, BS/128);
    gemm_mma<<<g1, 256, GEMM_SMEM>>>(yln, W1, h1, BS, MLPD, Dd, b1, nullptr, 1);

    // 9. MLP down + bias + residual -> d_out[0 .. BS*D)
    dim3 g2(Dd/128, BS/128);
    gemm_mma<<<g2, 256, GEMM_SMEM>>>(h1, W2, out, BS, Dd, MLPD, b2, x1, 0);

    // 10/11. auxiliary bucket loss -> d_out[BS*D]
    bsum_kernel<<<2*Hh*NBb, 256>>>(qb, kb, bsum);
    loss_kernel<<<1, 256>>>(bsum, out);
}

// round 9
// speedup vs baseline: 2.6743x; 1.7723x over previous
#include <cuda_runtime.h>
#include <cuda_bf16.h>
#include <cuda_fp16.h>
#include <cstdint>

#define Bb 2
#define Ss 2048
#define Dd 1024
#define Hh 16
#define DHh 64
#define NBb 32
#define MLPD 4096
#define BS (Bb*Ss)          // 4096
#define DA 96               // augmented attention dim (64 + 32)
#define LN_EPS 1e-6f
#define LOG2E_over8 0.18033688f
#define LOG2E_tenth 0.14426950f

// ===================== helpers =============================================
__device__ __forceinline__ uint32_t smem_u32(const void* p) {
    uint32_t a;
    asm("{ .reg .u64 t; cvta.to.shared.u64 t, %1; cvt.u32.u64 %0, t; }" : "=r"(a) : "l"(p));
    return a;
}
#define LDSM_X4(r, addr) \
    asm volatile("ldmatrix.sync.aligned.m8n8.x4.shared.b16 {%0,%1,%2,%3}, [%4];" \
        : "=r"((r)[0]), "=r"((r)[1]), "=r"((r)[2]), "=r"((r)[3]) : "r"(addr))
#define LDSM_X4T(r, addr) \
    asm volatile("ldmatrix.sync.aligned.m8n8.x4.trans.shared.b16 {%0,%1,%2,%3}, [%4];" \
        : "=r"((r)[0]), "=r"((r)[1]), "=r"((r)[2]), "=r"((r)[3]) : "r"(addr))
#define MMA_BF16(c, a, b0, b1) \
    asm volatile("mma.sync.aligned.m16n8k16.row.col.f32.bf16.bf16.f32 " \
        "{%0,%1,%2,%3}, {%4,%5,%6,%7}, {%8,%9}, {%0,%1,%2,%3};" \
        : "+f"((c)[0]), "+f"((c)[1]), "+f"((c)[2]), "+f"((c)[3]) \
        : "r"((a)[0]), "r"((a)[1]), "r"((a)[2]), "r"((a)[3]), "r"(b0), "r"(b1))
#define MMA_F16(c, a, b0, b1) \
    asm volatile("mma.sync.aligned.m16n8k16.row.col.f32.f16.f16.f32 " \
        "{%0,%1,%2,%3}, {%4,%5,%6,%7}, {%8,%9}, {%0,%1,%2,%3};" \
        : "+f"((c)[0]), "+f"((c)[1]), "+f"((c)[2]), "+f"((c)[3]) \
        : "r"((a)[0]), "r"((a)[1]), "r"((a)[2]), "r"((a)[3]), "r"(b0), "r"(b1))

// ------------------- scratch (static device allocations) -------------------
__device__ float g_xln[BS*Dd];
__device__ float g_q  [BS*Dd];
__device__ float g_k  [BS*Dd];
__device__ float g_v  [BS*Dd];
__device__ float g_qb [BS*Hh*NBb];
__device__ float g_kb [BS*Hh*NBb];
__device__ float g_AO [BS*Dd];
__device__ float g_x1 [BS*Dd];
__device__ float g_yln[BS*Dd];
__device__ float g_h1 [(long)BS*MLPD];
__device__ float g_bsum[2*Hh*NBb];
// fp16 attention operands
__device__ __half g_QAh[(long)Bb*Hh*Ss*DA];
__device__ __half g_QAl[(long)Bb*Hh*Ss*DA];
__device__ __half g_KTh[(long)Bb*Hh*DA*Ss];
__device__ __half g_KTl[(long)Bb*Hh*DA*Ss];
__device__ __half g_Vh [(long)Bb*Hh*Ss*DHh];

// ------------------------------- LayerNorm ---------------------------------
__global__ void ln_kernel(const float* __restrict__ x, const float* __restrict__ g,
                          const float* __restrict__ bt, float* __restrict__ out)
{
    int row = blockIdx.x;
    int tid = threadIdx.x;                     // 256 threads, D/4 = 256 float4
    const float4* xr = (const float4*)(x + (long)row*Dd);
    float4 v = xr[tid];
    float s  = v.x+v.y+v.z+v.w;
    float s2 = v.x*v.x+v.y*v.y+v.z*v.z+v.w*v.w;
    __shared__ float sh[16];
    #pragma unroll
    for (int off=16; off; off>>=1) {
        s  += __shfl_xor_sync(0xffffffffu, s,  off);
        s2 += __shfl_xor_sync(0xffffffffu, s2, off);
    }
    int wid = tid >> 5;
    if ((tid & 31) == 0) { sh[wid] = s; sh[8+wid] = s2; }
    __syncthreads();
    if (tid < 32) {
        float a  = (tid < 8) ? sh[tid]   : 0.f;
        float b2 = (tid < 8) ? sh[8+tid] : 0.f;
        #pragma unroll
        for (int off=4; off; off>>=1) {
            a  += __shfl_xor_sync(0xffffffffu, a,  off);
            b2 += __shfl_xor_sync(0xffffffffu, b2, off);
        }
        if (tid == 0) { sh[0] = a; sh[1] = b2; }
    }
    __syncthreads();
    float mu  = sh[0] * (1.f/Dd);
    float var = sh[1] * (1.f/Dd) - mu*mu;
    float inv = rsqrtf(var + LN_EPS);
    float4 gg = ((const float4*)g)[tid];
    float4 bb = ((const float4*)bt)[tid];
    float4 r;
    r.x = (v.x-mu)*inv*gg.x + bb.x;
    r.y = (v.y-mu)*inv*gg.y + bb.y;
    r.z = (v.z-mu)*inv*gg.z + bb.z;
    r.w = (v.w-mu)*inv*gg.w + bb.w;
    ((float4*)(out + (long)row*Dd))[tid] = r;
}

// ==================== bf16x3 mma.sync GEMM =================================
#define SWA 40
#define SWB 136
#define ASTG (128*SWA)
#define BSTG (32*SWB)
#define GEMM_SMEM ((2*ASTG*2 + 2*BSTG*2) * 2)

__device__ __forceinline__ void split_sts(const float* p,
                                          __nv_bfloat16* hiDst, __nv_bfloat16* loDst)
{
    __align__(16) __nv_bfloat16 hh[16], ll[16];
    #pragma unroll
    for (int i = 0; i < 16; i++) {
        float x = p[i];
        __nv_bfloat16 h = __float2bfloat16_rn(x);
        hh[i] = h;
        ll[i] = __float2bfloat16_rn(x - __bfloat162float(h));
    }
    ((uint4*)hiDst)[0] = ((uint4*)hh)[0];
    ((uint4*)hiDst)[1] = ((uint4*)hh)[1];
    ((uint4*)loDst)[0] = ((uint4*)ll)[0];
    ((uint4*)loDst)[1] = ((uint4*)ll)[1];
}

__global__ __launch_bounds__(256, 1)
void gemm_mma(const float* __restrict__ A, const float* __restrict__ Bw,
              float* __restrict__ C, int M, int N, int K,
              const float* __restrict__ bias, const float* __restrict__ res, int relu)
{
    extern __shared__ __nv_bfloat16 smh[];
    __nv_bfloat16* sAh = smh;
    __nv_bfloat16* sAl = smh + 2*ASTG;
    __nv_bfloat16* sBh = smh + 4*ASTG;
    __nv_bfloat16* sBl = smh + 4*ASTG + 2*BSTG;
    const uint32_t smbase = smem_u32(smh);

    const int tid  = threadIdx.x;
    const int lane = tid & 31;
    const int wid  = tid >> 5;
    const int m0 = blockIdx.y * 128, n0 = blockIdx.x * 128;
    const int m0w = (wid & 3) * 32, n0w = (wid >> 2) * 64;

    const int arow = tid >> 1, akh = (tid & 1) * 16;
    const int bkr  = tid >> 3, bns = (tid & 7) * 16;
    const float* Ag0 = A  + (long)(m0 + arow)*K + akh;
    const float* Bg0 = Bw + (long)bkr*N + n0 + bns;

    float acc[2][8][4];
    #pragma unroll
    for (int i=0;i<2;i++)
        #pragma unroll
        for (int j=0;j<8;j++)
            #pragma unroll
            for (int t=0;t<4;t++) acc[i][j][t] = 0.f;

    const int KC = K >> 5;
    float pa[16], pb[16];

    #pragma unroll
    for (int i=0;i<4;i++) *(float4*)&pa[i*4] = *(const float4*)(Ag0 + i*4);
    #pragma unroll
    for (int i=0;i<4;i++) *(float4*)&pb[i*4] = *(const float4*)(Bg0 + i*4);
    split_sts(pa, sAh + arow*SWA + akh, sAl + arow*SWA + akh);
    split_sts(pb, sBh + bkr*SWB + bns, sBl + bkr*SWB + bns);
    __syncthreads();

    const int arow_l = m0w + (lane & 15);
    const int acol_l = (lane >> 4) << 3;
    const int bkr_l  = ((lane >> 3) & 1) * 8 + (lane & 7);
    const int bnc_l  = n0w + ((lane >> 4) << 3);

    for (int c = 0; c < KC; c++) {
        const int st = c & 1;
        if (c + 1 < KC) {
            const float* Agn = Ag0 + (c+1)*32;
            const float* Bgn = Bg0 + (long)(c+1)*32*N;
            #pragma unroll
            for (int i=0;i<4;i++) *(float4*)&pa[i*4] = *(const float4*)(Agn + i*4);
            #pragma unroll
            for (int i=0;i<4;i++) *(float4*)&pb[i*4] = *(const float4*)(Bgn + i*4);
        }

        const uint32_t baseAh = smbase + (uint32_t)(st*ASTG)*2;
        const uint32_t baseAl = baseAh + (uint32_t)(2*ASTG)*2;
        const uint32_t baseBh = smbase + (uint32_t)(4*ASTG + st*BSTG)*2;
        const uint32_t baseBl = baseBh + (uint32_t)(2*BSTG)*2;

        #pragma unroll
        for (int ks = 0; ks < 2; ks++) {
            const int kst = ks*16;
            uint32_t ah[2][4], al[2][4];
            {
                uint32_t a0 = baseAh + (uint32_t)(arow_l*SWA + kst + acol_l)*2;
                LDSM_X4(ah[0], a0);
                LDSM_X4(ah[1], a0 + 16*SWA*2);
                uint32_t a1 = baseAl + (uint32_t)(arow_l*SWA + kst + acol_l)*2;
                LDSM_X4(al[0], a1);
                LDSM_X4(al[1], a1 + 16*SWA*2);
            }
            #pragma unroll
            for (int ntp = 0; ntp < 4; ntp++) {
                uint32_t bh[4], bl[4];
                uint32_t boff = (uint32_t)((kst + bkr_l)*SWB + bnc_l + ntp*16)*2;
                LDSM_X4T(bh, baseBh + boff);
                LDSM_X4T(bl, baseBl + boff);
                #pragma unroll
                for (int mt = 0; mt < 2; mt++) {
                    MMA_BF16(acc[mt][2*ntp],   ah[mt], bh[0], bh[1]);
                    MMA_BF16(acc[mt][2*ntp],   ah[mt], bl[0], bl[1]);
                    MMA_BF16(acc[mt][2*ntp],   al[mt], bh[0], bh[1]);
                    MMA_BF16(acc[mt][2*ntp+1], ah[mt], bh[2], bh[3]);
                    MMA_BF16(acc[mt][2*ntp+1], ah[mt], bl[2], bl[3]);
                    MMA_BF16(acc[mt][2*ntp+1], al[mt], bh[2], bh[3]);
                }
            }
        }

        if (c + 1 < KC) {
            const int s2 = st ^ 1;
            split_sts(pa, sAh + s2*ASTG + arow*SWA + akh, sAl + s2*ASTG + arow*SWA + akh);
            split_sts(pb, sBh + s2*BSTG + bkr*SWB + bns, sBl + s2*BSTG + bkr*SWB + bns);
        }
        __syncthreads();
    }

    const int gid = lane >> 2, tig = lane & 3;
    #pragma unroll
    for (int mt = 0; mt < 2; mt++) {
        #pragma unroll
        for (int nt = 0; nt < 8; nt++) {
            long row = m0 + m0w + mt*16 + gid;
            int  col = n0 + n0w + nt*8 + tig*2;
            float2 v0 = make_float2(acc[mt][nt][0], acc[mt][nt][1]);
            float2 v1 = make_float2(acc[mt][nt][2], acc[mt][nt][3]);
            if (bias) {
                float2 bv = *(const float2*)&bias[col];
                v0.x += bv.x; v0.y += bv.y; v1.x += bv.x; v1.y += bv.y;
            }
            if (relu) {
                v0.x = fmaxf(v0.x, 0.f); v0.y = fmaxf(v0.y, 0.f);
                v1.x = fmaxf(v1.x, 0.f); v1.y = fmaxf(v1.y, 0.f);
            }
            if (res) {
                float2 r0 = *(const float2*)&res[row*N + col];
                float2 r1 = *(const float2*)&res[(row+8)*N + col];
                v0.x += r0.x; v0.y += r0.y; v1.x += r1.x; v1.y += r1.y;
            }
            *(float2*)&C[row*N + col]     = v0;
            *(float2*)&C[(row+8)*N + col] = v1;
        }
    }
}

// ------------------------- bucket softmax (qb / kb) -------------------------
__global__ void bucket_kernel(const float* __restrict__ qk, const float* __restrict__ Wh,
                              float* __restrict__ out)
{
    int gw   = blockIdx.x * (blockDim.x >> 5) + (threadIdx.x >> 5);
    int lane = threadIdx.x & 31;
    if (gw >= BS*Hh) return;
    int h  = gw % Hh;
    int bs = gw / Hh;
    const float* qrow = qk + (long)bs*Dd + h*DHh;
    const float* W    = Wh + (long)h*DHh*NBb;
    float acc = 0.f;
    #pragma unroll
    for (int f=0; f<DHh; f++) acc += qrow[f] * W[f*NBb + lane];
    float m = acc;
    #pragma unroll
    for (int off=16; off; off>>=1) m = fmaxf(m, __shfl_xor_sync(0xffffffffu, m, off));
    float e = __expf(acc - m);
    float s = e;
    #pragma unroll
    for (int off=16; off; off>>=1) s += __shfl_xor_sync(0xffffffffu, s, off);
    out[(long)gw*NBb + lane] = e / s;
}

// ------------------ prep: fp16 hi/lo attention operands ---------------------
// QA[bh][s][96] = concat(q * log2e/8, qb * 0.1*log2e), split hi/lo fp16
__global__ void prep_qa(const float* __restrict__ q, const float* __restrict__ qb,
                        __half* __restrict__ QAh, __half* __restrict__ QAl)
{
    long i = (long)blockIdx.x*256 + threadIdx.x;
    const long total = (long)Bb*Hh*Ss*DA;
    if (i >= total) return;
    int  j  = (int)(i % DA);
    long r  = i / DA;
    int  s  = (int)(r % Ss);
    int  bh = (int)(r / Ss);
    int  h  = bh & 15, b = bh >> 4;
    float val = (j < DHh)
        ? q[((long)(b*Ss + s))*Dd + h*DHh + j] * LOG2E_over8
        : qb[(((long)(b*Ss + s))*Hh + h)*NBb + j - DHh] * LOG2E_tenth;
    __half hi = __float2half_rn(val);
    __half lo = __float2half_rn(val - __half2float(hi));
    QAh[i] = hi; QAl[i] = lo;
}

// KT[bh][da][s]: transposed K-augmented (k then kb), split hi/lo
__global__ void prep_kt(const float* __restrict__ k, const float* __restrict__ kb,
                        __half* __restrict__ KTh, __half* __restrict__ KTl)
{
    __shared__ float t[32][33];
    int bh = blockIdx.z, b = bh >> 4, h = bh & 15;
    int j0 = blockIdx.y*32, s0 = blockIdx.x*32;
    int tx = threadIdx.x & 31, ty = threadIdx.x >> 5;
    #pragma unroll
    for (int i = 0; i < 32; i += 8) {
        int s = s0 + ty + i;
        float val = (j0 < DHh)
            ? k[((long)(b*Ss + s))*Dd + h*DHh + j0 + tx]
            : kb[(((long)(b*Ss + s))*Hh + h)*NBb + (j0 - DHh) + tx];
        t[ty+i][tx] = val;
    }
    __syncthreads();
    #pragma unroll
    for (int i = 0; i < 32; i += 8) {
        int j = j0 + ty + i;
        float val = t[tx][ty+i];
        __half hi = __float2half_rn(val);
        __half lo = __float2half_rn(val - __half2float(hi));
        long o = ((long)bh*DA + j)*Ss + s0 + tx;
        KTh[o] = hi; KTl[o] = lo;
    }
}

// V[bh][s][64] fp16 (single plane)
__global__ void prep_v(const float* __restrict__ v, __half* __restrict__ Vhh)
{
    long i = (long)blockIdx.x*256 + threadIdx.x;
    const long total = (long)Bb*Hh*Ss*DHh;
    if (i >= total) return;
    int  j  = (int)(i % DHh);
    long r  = i / DHh;
    int  s  = (int)(r % Ss);
    int  bh = (int)(r / Ss);
    int  h  = bh & 15, b = bh >> 4;
    Vhh[i] = __float2half_rn(v[((long)(b*Ss + s))*Dd + h*DHh + j]);
}

// ------------------------ tensor-core flash attention -----------------------
// CTA: 128 q-rows x one (b,h); 8 warps, each m16 x full k-width 64.
// No max subtraction (scores bounded); exp2 via MUFU f16x2; PV fp16.
#define SWQ 104
#define SWK 72
#define SWV 72
#define OFF_QL (128*SWQ)            // halfs
#define OFF_KH (2*128*SWQ)
#define OFF_KL (OFF_KH + DA*SWK)
#define OFF_V  (OFF_KL + DA*SWK)
#define FLASH_SMEM ((OFF_V + 64*SWV)*2)   // bytes = 90112

__global__ __launch_bounds__(256, 2)
void flash_mma(const __half* __restrict__ QAh, const __half* __restrict__ QAl,
               const __half* __restrict__ KTh, const __half* __restrict__ KTl,
               const __half* __restrict__ Vhh, float* __restrict__ AO)
{
    extern __shared__ __half smf[];
    const uint32_t sb = smem_u32(smf);
    const int tid = threadIdx.x, lane = tid & 31, wid = tid >> 5;
    const int bh = blockIdx.y, b = bh >> 4, h = bh & 15;
    const int q0 = blockIdx.x * 128;

    // stage Q tile (resident)
    {
        const __half* Qhp = QAh + ((long)bh*Ss + q0)*DA;
        const __half* Qlp = QAl + ((long)bh*Ss + q0)*DA;
        for (int i = tid; i < 128*12; i += 256) {
            int r = i/12, seg = i%12;
            *(uint4*)&smf[r*SWQ + seg*8]          = *(const uint4*)&Qhp[(long)r*DA + seg*8];
            *(uint4*)&smf[OFF_QL + r*SWQ + seg*8] = *(const uint4*)&Qlp[(long)r*DA + seg*8];
        }
    }

    float accO[8][4];
    #pragma unroll
    for (int i=0;i<8;i++) { accO[i][0]=0.f; accO[i][1]=0.f; accO[i][2]=0.f; accO[i][3]=0.f; }
    float rsum0 = 0.f, rsum1 = 0.f;

    const int wq0  = wid * 16;
    const int arow = wq0 + (lane & 15);
    const int acol = (lane >> 4) << 3;
    const int bkr  = ((lane >> 3) & 1) * 8 + (lane & 7);
    const int bnc  = (lane >> 4) << 3;
    const uint32_t qh_base = sb + (uint32_t)(arow*SWQ + acol)*2;
    const uint32_t ql_base = qh_base + (uint32_t)OFF_QL*2;

    const __half* KThp = KTh + (long)bh*DA*Ss;
    const __half* KTlp = KTl + (long)bh*DA*Ss;
    const __half* Vp   = Vhh + (long)bh*Ss*DHh;

    for (int s0 = 0; s0 < Ss; s0 += 64) {
        __syncthreads();
        // producer: K tile [96][64] hi/lo + V tile [64][64]
        for (int i = tid; i < DA*8; i += 256) {
            int r = i >> 3, seg = i & 7;
            *(uint4*)&smf[OFF_KH + r*SWK + seg*8] = *(const uint4*)&KThp[(long)r*Ss + s0 + seg*8];
            *(uint4*)&smf[OFF_KL + r*SWK + seg*8] = *(const uint4*)&KTlp[(long)r*Ss + s0 + seg*8];
        }
        for (int i = tid; i < 64*8; i += 256) {
            int r = i >> 3, seg = i & 7;
            *(uint4*)&smf[OFF_V + r*SWV + seg*8] = *(const uint4*)&Vp[(long)(s0 + r)*DHh + seg*8];
        }
        __syncthreads();

        // S = QA * KA^T (fp16 3-term, log2 domain)
        float accs[8][4];
        #pragma unroll
        for (int i=0;i<8;i++) { accs[i][0]=0.f; accs[i][1]=0.f; accs[i][2]=0.f; accs[i][3]=0.f; }
        #pragma unroll
        for (int ks = 0; ks < 6; ks++) {
            uint32_t qh[4], ql[4];
            LDSM_X4(qh, qh_base + (uint32_t)(ks*16)*2);
            LDSM_X4(ql, ql_base + (uint32_t)(ks*16)*2);
            #pragma unroll
            for (int ntp = 0; ntp < 4; ntp++) {
                uint32_t kh[4], kl[4];
                uint32_t off = (uint32_t)((ks*16 + bkr)*SWK + bnc + ntp*16)*2;
                LDSM_X4T(kh, sb + (uint32_t)OFF_KH*2 + off);
                LDSM_X4T(kl, sb + (uint32_t)OFF_KL*2 + off);
                MMA_F16(accs[2*ntp],   qh, kh[0], kh[1]);
                MMA_F16(accs[2*ntp],   qh, kl[0], kl[1]);
                MMA_F16(accs[2*ntp],   ql, kh[0], kh[1]);
                MMA_F16(accs[2*ntp+1], qh, kh[2], kh[3]);
                MMA_F16(accs[2*ntp+1], qh, kl[2], kl[3]);
                MMA_F16(accs[2*ntp+1], ql, kh[2], kh[3]);
            }
        }

        // P = exp2(S) in fp16 packed; rowsum over the SAME fp16 values
        uint32_t P[4][4];
        __half2 rsA = __float2half2_rn(0.f), rsB = __float2half2_rn(0.f);
        #pragma unroll
        for (int nt = 0; nt < 8; nt++) {
            __half2 p01 = h2exp2(__floats2half2_rn(accs[nt][0], accs[nt][1]));
            __half2 p23 = h2exp2(__floats2half2_rn(accs[nt][2], accs[nt][3]));
            P[nt>>1][(nt&1)*2+0] = *reinterpret_cast<uint32_t*>(&p01);
            P[nt>>1][(nt&1)*2+1] = *reinterpret_cast<uint32_t*>(&p23);
            rsA = __hadd2(rsA, p01);
            rsB = __hadd2(rsB, p23);
        }
        float sf0 = __low2float(rsA) + __high2float(rsA);
        float sf1 = __low2float(rsB) + __high2float(rsB);
        sf0 += __shfl_xor_sync(0xffffffffu, sf0, 1);
        sf0 += __shfl_xor_sync(0xffffffffu, sf0, 2);
        sf1 += __shfl_xor_sync(0xffffffffu, sf1, 1);
        sf1 += __shfl_xor_sync(0xffffffffu, sf1, 2);
        rsum0 += sf0; rsum1 += sf1;

        // O += P * V (fp16)
        #pragma unroll
        for (int kt = 0; kt < 4; kt++) {
            #pragma unroll
            for (int vtp = 0; vtp < 4; vtp++) {
                uint32_t vv[4];
                LDSM_X4T(vv, sb + (uint32_t)OFF_V*2 +
                             (uint32_t)((kt*16 + bkr)*SWV + bnc + vtp*16)*2);
                MMA_F16(accO[2*vtp],   P[kt], vv[0], vv[1]);
                MMA_F16(accO[2*vtp+1], P[kt], vv[2], vv[3]);
            }
        }
    }

    // epilogue: normalize and write AO[b][s][h*64+dh]
    const float i0 = 1.f / rsum0, i1 = 1.f / rsum1;
    const int gid = lane >> 2, tig = lane & 3;
    const long row0 = (long)(b*Ss + q0 + wq0 + gid);
    #pragma unroll
    for (int nt = 0; nt < 8; nt++) {
        int col = h*DHh + nt*8 + tig*2;
        *(float2*)&AO[row0*Dd + col]     = make_float2(accO[nt][0]*i0, accO[nt][1]*i0);
        *(float2*)&AO[(row0+8)*Dd + col] = make_float2(accO[nt][2]*i1, accO[nt][3]*i1);
    }
}

// ---------------------------- bucket load-balance loss ----------------------
__global__ void bsum_kernel(const float* __restrict__ qb, const float* __restrict__ kb,
                            float* __restrict__ bsum)
{
    int id = blockIdx.x;
    const float* src = (id < Hh*NBb) ? qb : kb;
    int hn = id % (Hh*NBb);
    float s = 0.f;
    for (int r = threadIdx.x; r < BS; r += blockDim.x)
        s += src[(long)r*(Hh*NBb) + hn];
    __shared__ float sh[8];
    #pragma unroll
    for (int off=16; off; off>>=1) s += __shfl_xor_sync(0xffffffffu, s, off);
    int wid = threadIdx.x >> 5;
    if ((threadIdx.x & 31) == 0) sh[wid] = s;
    __syncthreads();
    if (threadIdx.x < 8) {
        float a = sh[threadIdx.x];
        #pragma unroll
        for (int off=4; off; off>>=1) a += __shfl_xor_sync(0xffffffffu, a, off, 8);
        if (threadIdx.x == 0) bsum[id] = a / (float)BS;
    }
}

__global__ void loss_kernel(const float* __restrict__ bsum, float* __restrict__ out)
{
    float t = 0.f;
    for (int i = threadIdx.x; i < 2*Hh*NBb; i += blockDim.x) {
        float v = bsum[i]; t += v*v;
    }
    __shared__ float sh[8];
    #pragma unroll
    for (int off=16; off; off>>=1) t += __shfl_xor_sync(0xffffffffu, t, off);
    int wid = threadIdx.x >> 5;
    if ((threadIdx.x & 31) == 0) sh[wid] = t;
    __syncthreads();
    if (threadIdx.x == 0) {
        float tot = 0.f;
        for (int i=0;i<8;i++) tot += sh[i];
        out[(long)BS*Dd] = 0.5f * (float)NBb / (float)Hh * tot;
    }
}

// --------------------------------- launch -----------------------------------
extern "C" void kernel_launch(void* const* d_in, const int* in_sizes, int n_in,
                              void* d_out, int out_size)
{
    const float* inputs = (const float*)d_in[0];
    const float* ln1_g  = (const float*)d_in[1];
    const float* ln1_b  = (const float*)d_in[2];
    const float* Wq     = (const float*)d_in[3];
    const float* Wk     = (const float*)d_in[4];
    const float* Wv     = (const float*)d_in[5];
    const float* Whq    = (const float*)d_in[6];
    const float* Whk    = (const float*)d_in[7];
    const float* Wo     = (const float*)d_in[8];
    const float* ln2_g  = (const float*)d_in[9];
    const float* ln2_b  = (const float*)d_in[10];
    const float* W1     = (const float*)d_in[11];
    const float* b1     = (const float*)d_in[12];
    const float* W2     = (const float*)d_in[13];
    const float* b2     = (const float*)d_in[14];
    float* out = (float*)d_out;

    float *xln, *q, *k, *v, *qb, *kb, *AO, *x1, *yln, *h1, *bsum;
    __half *QAh, *QAl, *KTh, *KTl, *Vhh;
    cudaGetSymbolAddress((void**)&xln, g_xln);
    cudaGetSymbolAddress((void**)&q,   g_q);
    cudaGetSymbolAddress((void**)&k,   g_k);
    cudaGetSymbolAddress((void**)&v,   g_v);
    cudaGetSymbolAddress((void**)&qb,  g_qb);
    cudaGetSymbolAddress((void**)&kb,  g_kb);
    cudaGetSymbolAddress((void**)&AO,  g_AO);
    cudaGetSymbolAddress((void**)&x1,  g_x1);
    cudaGetSymbolAddress((void**)&yln, g_yln);
    cudaGetSymbolAddress((void**)&h1,  g_h1);
    cudaGetSymbolAddress((void**)&bsum,g_bsum);
    cudaGetSymbolAddress((void**)&QAh, g_QAh);
    cudaGetSymbolAddress((void**)&QAl, g_QAl);
    cudaGetSymbolAddress((void**)&KTh, g_KTh);
    cudaGetSymbolAddress((void**)&KTl, g_KTl);
    cudaGetSymbolAddress((void**)&Vhh, g_Vh);

    cudaFuncSetAttribute(gemm_mma, cudaFuncAttributeMaxDynamicSharedMemorySize, GEMM_SMEM);
    cudaFuncSetAttribute(flash_mma, cudaFuncAttributeMaxDynamicSharedMemorySize, FLASH_SMEM);

    // 1. LN1
    ln_kernel<<<BS, 256>>>(inputs, ln1_g, ln1_b, xln);

    // 2. QKV projections
    dim3 gqkv(Dd/128, BS/128);
    gemm_mma<<<gqkv, 256, GEMM_SMEM>>>(xln, Wq, q, BS, Dd, Dd, nullptr, nullptr, 0);
    gemm_mma<<<gqkv, 256, GEMM_SMEM>>>(xln, Wk, k, BS, Dd, Dd, nullptr, nullptr, 0);
    gemm_mma<<<gqkv, 256, GEMM_SMEM>>>(xln, Wv, v, BS, Dd, Dd, nullptr, nullptr, 0);

    // 3. bucket softmaxes
    int nwarp_blocks = (BS*Hh) / 8;
    bucket_kernel<<<nwarp_blocks, 256>>>(q, Whq, qb);
    bucket_kernel<<<nwarp_blocks, 256>>>(k, Whk, kb);

    // 4. fp16 operand prep
    {
        long totA = (long)Bb*Hh*Ss*DA;
        prep_qa<<<(int)((totA + 255)/256), 256>>>(q, qb, QAh, QAl);
        prep_kt<<<dim3(Ss/32, DA/32, Bb*Hh), 256>>>(k, kb, KTh, KTl);
        long totV = (long)Bb*Hh*Ss*DHh;
        prep_v<<<(int)((totV + 255)/256), 256>>>(v, Vhh);
    }

    // 5. tensor-core flash attention
    flash_mma<<<dim3(Ss/128, Bb*Hh), 256, FLASH_SMEM>>>(QAh, QAl, KTh, KTl, Vhh, AO);

    // 6. output projection + residual -> x1
    gemm_mma<<<gqkv, 256, GEMM_SMEM>>>(AO, Wo, x1, BS, Dd, Dd, nullptr, inputs, 0);

    // 7. LN2
    ln_kernel<<<BS, 256>>>(x1, ln2_g, ln2_b, yln);

    // 8. MLP up + bias + relu
    dim3 g1(MLPD/128, BS/128);
    gemm_mma<<<g1, 256, GEMM_SMEM>>>(yln, W1, h1, BS, MLPD, Dd, b1, nullptr, 1);

    // 9. MLP down + bias + residual -> d_out
    dim3 g2(Dd/128, BS/128);
    gemm_mma<<<g2, 256, GEMM_SMEM>>>(h1, W2, out, BS, Dd, MLPD, b2, x1, 0);

    // 10/11. auxiliary bucket loss -> d_out[BS*D]
    bsum_kernel<<<2*Hh*NBb, 256>>>(qb, kb, bsum);
    loss_kernel<<<1, 256>>>(bsum, out);
}